// round 4
// baseline (speedup 1.0000x reference)
#include <cuda_runtime.h>
#include <cstdint>
#include <math.h>

// ---------------- problem constants (fixed by setup_inputs) ----------------
#define ZDIM 256
#define HID  128
#define NL   6
#define BB   2
#define IMG  64
#define HW   (IMG*IMG)          // 4096
#define SS   12
#define NRAYS (BB*HW)           // 8192
#define NPTS  (NRAYS*SS)        // 98304
#define FP_DIM (NL*HID)         // 768

#define AS_STRIDE 132           // 128 + 4 pad

// zc = -1/tan(deg2rad(12)/2), computed in double
#define ZC (-9.514364454222587f)

// ---------------- packed f32x2 helpers (sm_103a) ----------------------------
#define PACKF2(out, lo, hi) \
    asm("mov.b64 %0, {%1, %2};" : "=l"(out) : "f"(lo), "f"(hi))
#define UNPACKF2(lo, hi, in) \
    asm("mov.b64 {%0, %1}, %2;" : "=f"(lo), "=f"(hi) : "l"(in))
#define FMAF2(acc, a, b) \
    asm("fma.rn.f32x2 %0, %1, %2, %3;" : "=l"(acc) : "l"(a), "l"(b), "l"(acc))

// ---------------- device scratch (no allocations allowed) ------------------
__device__ float g_freqs[BB*FP_DIM];
__device__ float g_phases[BB*FP_DIM];
__device__ float g_points[NPTS*3];     // coarse world points
__device__ float g_zvals[NPTS];        // coarse z (with perturbation)
__device__ float g_dirs[NRAYS*3];      // world-space ray dirs
__device__ float g_rgbs_c[NPTS*4];     // coarse rgb+sigma
__device__ float g_finez[NPTS];        // fine z samples
__device__ float g_points_f[NPTS*3];   // fine world points
__device__ float g_rgbs_f[NPTS*4];     // fine rgb+sigma

// ---------------- Threefry-2x32-20 (matches JAX) ---------------------------
__host__ __device__ static inline void tf2x32(uint32_t k0, uint32_t k1,
                                              uint32_t& x0, uint32_t& x1) {
    uint32_t ks2 = k0 ^ k1 ^ 0x1BD11BDAu;
    x0 += k0; x1 += k1;
#define TF_RND(r) { x0 += x1; x1 = (x1 << (r)) | (x1 >> (32 - (r))); x1 ^= x0; }
    TF_RND(13) TF_RND(15) TF_RND(26) TF_RND(6)
    x0 += k1;  x1 += ks2 + 1u;
    TF_RND(17) TF_RND(29) TF_RND(16) TF_RND(24)
    x0 += ks2; x1 += k0 + 2u;
    TF_RND(13) TF_RND(15) TF_RND(26) TF_RND(6)
    x0 += k0;  x1 += k1 + 3u;
    TF_RND(17) TF_RND(29) TF_RND(16) TF_RND(24)
    x0 += k1;  x1 += ks2 + 4u;
    TF_RND(13) TF_RND(15) TF_RND(26) TF_RND(6)
    x0 += ks2; x1 += k0 + 5u;
#undef TF_RND
}

// JAX partitionable random bits: counter = 64-bit index (hi=0), bits = o0 ^ o1
__device__ static inline float jax_uniform(uint32_t k0, uint32_t k1, uint32_t idx) {
    uint32_t x0 = 0u, x1 = idx;
    tf2x32(k0, k1, x0, x1);
    uint32_t bits = x0 ^ x1;
    return __uint_as_float((bits >> 9) | 0x3f800000u) - 1.0f;
}

// ---------------- kernel 1: mapping network --------------------------------
__global__ void map_kernel(const float* __restrict__ z,
                           const float* __restrict__ w0, const float* __restrict__ b0,
                           const float* __restrict__ w1, const float* __restrict__ b1,
                           const float* __restrict__ w2, const float* __restrict__ b2) {
    __shared__ float sh[ZDIM];
    int b = blockIdx.x, t = threadIdx.x;
    sh[t] = z[b*ZDIM + t];
    __syncthreads();
    float acc = b0[t];
    for (int k = 0; k < ZDIM; k++) acc = fmaf(sh[k], w0[k*256 + t], acc);
    float v = (acc >= 0.f) ? acc : 0.2f*acc;
    __syncthreads(); sh[t] = v; __syncthreads();
    acc = b1[t];
    for (int k = 0; k < 256; k++) acc = fmaf(sh[k], w1[k*256 + t], acc);
    v = (acc >= 0.f) ? acc : 0.2f*acc;
    __syncthreads(); sh[t] = v; __syncthreads();
    for (int j = t; j < FP_DIM*2; j += 256) {
        float a = b2[j];
        for (int k = 0; k < 256; k++) a = fmaf(sh[k], w2[k*(FP_DIM*2) + j], a);
        if (j < FP_DIM) g_freqs[b*FP_DIM + j] = a*15.0f + 30.0f;
        else            g_phases[b*FP_DIM + (j - FP_DIM)] = a;
    }
}

// ---------------- kernel 2: ray generation + coarse points -----------------
__global__ void raygen_kernel(const float* __restrict__ c2w,
                              uint32_t kp0, uint32_t kp1) {
    int ray = blockIdx.x * blockDim.x + threadIdx.x;
    if (ray >= NRAYS) return;
    int b = ray / HW, r = ray % HW;
    int h = r / IMG, w = r % IMG;
    float x = -1.0f + w * (2.0f/63.0f);
    float y =  1.0f - h * (2.0f/63.0f);
    float n  = sqrtf(x*x + y*y + ZC*ZC);
    float dx = x/n, dy = y/n, dz = ZC/n;
    const float* M = c2w + b*16;
    g_dirs[ray*3+0] = M[0]*dx + M[1]*dy + M[2]*dz;
    g_dirs[ray*3+1] = M[4]*dx + M[5]*dy + M[6]*dz;
    g_dirs[ray*3+2] = M[8]*dx + M[9]*dy + M[10]*dz;
    const float spacing = (1.12f - 0.88f) / 11.0f;
    for (int s = 0; s < SS; s++) {
        int idx = ray*SS + s;
        float u   = jax_uniform(kp0, kp1, (uint32_t)idx);
        float off = (u - 0.5f) * spacing;
        float zv  = 0.88f + s*spacing + off;
        float px = dx*zv, py = dy*zv, pz = dz*zv;
        g_points[idx*3+0] = M[0]*px + M[1]*py + M[2]*pz  + M[3];
        g_points[idx*3+1] = M[4]*px + M[5]*py + M[6]*pz  + M[7];
        g_points[idx*3+2] = M[8]*px + M[9]*py + M[10]*pz + M[11];
        g_zvals[idx] = zv;
    }
}

// ---------------- kernel 3/5: fused SIREN forward ---------------------------
__global__ void __launch_bounds__(256, 1)
siren_kernel(int fine,
             const float* __restrict__ fw, const float* __restrict__ fb,
             const float* __restrict__ hw_, const float* __restrict__ hb,
             const float* __restrict__ ow, const float* __restrict__ ob) {
    extern __shared__ float sm[];
    float* As = sm;                       // [128][132] activations, k-major
    float* Bs = sm + 128*AS_STRIDE;       // [128][132] weights
    float* fr = sm + 2*128*AS_STRIDE;     // 128
    float* ph = fr + 128;                 // 128
    float* bi = ph + 128;                 // 128

    const float* pts  = fine ? g_points_f : g_points;
    float*       outr = fine ? g_rgbs_f   : g_rgbs_c;

    int tid = threadIdx.x;
    int tx = tid & 15, ty = tid >> 4;
    int m0 = blockIdx.x * 128;
    int batch = m0 / (HW*SS);
    const float* frq = g_freqs  + batch*FP_DIM;
    const float* phs = g_phases + batch*FP_DIM;

    int mrow[8];
#pragma unroll
    for (int i = 0; i < 8; i++) mrow[i] = (i < 4) ? (ty*4 + i) : (64 + ty*4 + (i-4));

    // ---- first layer: 3 -> 128 ----
    {
        float* ptsh = Bs;           // 384
        float* fwsh = Bs + 512;     // 384
        float* fbsh = Bs + 1024;    // 128
        for (int i = tid; i < 384; i += 256) ptsh[i] = pts[m0*3 + i];
        for (int i = tid; i < 384; i += 256) fwsh[i] = fw[i];
        if (tid < 128) { fbsh[tid] = fb[tid]; fr[tid] = frq[tid]; ph[tid] = phs[tid]; }
        __syncthreads();
#pragma unroll
        for (int j = 0; j < 8; j++) {
            int n = (j < 4) ? (tx*4 + j) : (64 + tx*4 + (j-4));
            float w0v = fwsh[n], w1v = fwsh[128+n], w2v = fwsh[256+n];
            float bn = fbsh[n], fn = fr[n], pn = ph[n];
#pragma unroll
            for (int i = 0; i < 8; i++) {
                int m = mrow[i];
                float v = bn + ptsh[m*3]*w0v + ptsh[m*3+1]*w1v + ptsh[m*3+2]*w2v;
                As[n*AS_STRIDE + m] = sinf(fn*v + pn);
            }
        }
        __syncthreads();
    }

    // ---- hidden layers 1..5: 128 -> 128 with sin(freq*(xW+b)+phase) ----
    for (int l = 1; l < NL; l++) {
        const float* W = hw_ + (l-1)*HID*HID;
        for (int i = tid*4; i < HID*HID; i += 1024) {
            int k = i >> 7, n = i & 127;
            float4 v = *reinterpret_cast<const float4*>(W + i);
            *reinterpret_cast<float4*>(&Bs[k*AS_STRIDE + n]) = v;
        }
        if (tid < 128) {
            fr[tid] = frq[l*HID + tid];
            ph[tid] = phs[l*HID + tid];
            bi[tid] = hb[(l-1)*HID + tid];
        }
        __syncthreads();

        // packed accumulators: acc[i][j2] holds n-pair (2 floats) for m-row i
        unsigned long long acc[8][4];
#pragma unroll
        for (int i = 0; i < 8; i++)
#pragma unroll
            for (int j = 0; j < 4; j++) acc[i][j] = 0ull;

#pragma unroll 2
        for (int k = 0; k < HID; k++) {
            // B pairs come straight out of shared as aligned 64-bit loads
            ulonglong2 b0 = *reinterpret_cast<const ulonglong2*>(&Bs[k*AS_STRIDE + tx*4]);
            ulonglong2 b1 = *reinterpret_cast<const ulonglong2*>(&Bs[k*AS_STRIDE + 64 + tx*4]);
            float4 a0 = *reinterpret_cast<const float4*>(&As[k*AS_STRIDE + ty*4]);
            float4 a1 = *reinterpret_cast<const float4*>(&As[k*AS_STRIDE + 64 + ty*4]);
            float af[8] = {a0.x,a0.y,a0.z,a0.w,a1.x,a1.y,a1.z,a1.w};
            unsigned long long ad[8];
#pragma unroll
            for (int i = 0; i < 8; i++) PACKF2(ad[i], af[i], af[i]);
            unsigned long long bp[4] = {b0.x, b0.y, b1.x, b1.y};
#pragma unroll
            for (int i = 0; i < 8; i++) {
#pragma unroll
                for (int j = 0; j < 4; j++) FMAF2(acc[i][j], ad[i], bp[j]);
            }
        }
        __syncthreads();
#pragma unroll
        for (int j2 = 0; j2 < 4; j2++) {
            int nb = (j2 < 2) ? (tx*4 + j2*2) : (64 + tx*4 + (j2-2)*2);
            float f0 = fr[nb],   p0 = ph[nb],   c0 = bi[nb];
            float f1 = fr[nb+1], p1 = ph[nb+1], c1 = bi[nb+1];
#pragma unroll
            for (int i = 0; i < 8; i++) {
                float v0, v1;
                UNPACKF2(v0, v1, acc[i][j2]);
                int m = mrow[i];
                As[nb*AS_STRIDE + m]     = sinf(f0*(v0 + c0) + p0);
                As[(nb+1)*AS_STRIDE + m] = sinf(f1*(v1 + c1) + p1);
            }
        }
        __syncthreads();
    }

    // ---- output layer: 128 -> 4, sigmoid on rgb ----
    {
        float* owsh = Bs;          // 512
        float* obsh = Bs + 512;    // 4
        for (int i = tid; i < 512; i += 256) owsh[i] = ow[i];
        if (tid < 4) obsh[tid] = ob[tid];
        __syncthreads();
        for (int t2 = tid; t2 < 512; t2 += 256) {
            int m = t2 >> 2, j = t2 & 3;
            float a = obsh[j];
            for (int k = 0; k < HID; k++)
                a = fmaf(As[k*AS_STRIDE + m], owsh[k*4 + j], a);
            if (j < 3) a = 1.0f / (1.0f + expf(-a));
            outr[(m0 + m)*4 + j] = a;
        }
    }
}

// ---------------- kernel 4: coarse integration + inverse-CDF sampling ------
__global__ void sample_kernel(const float* __restrict__ c2w,
                              uint32_t kq0, uint32_t kq1) {
    int ray = blockIdx.x * blockDim.x + threadIdx.x;
    if (ray >= NRAYS) return;
    int b = ray / HW;
    int base = ray * SS;

    float z[SS], sg[SS];
    for (int s = 0; s < SS; s++) {
        z[s]  = g_zvals[base + s];
        sg[s] = g_rgbs_c[(base + s)*4 + 3];
    }
    // fancy_integration weights
    float wgt[SS]; float T = 1.0f;
    for (int s = 0; s < SS; s++) {
        float d = (s < SS-1) ? (z[s+1] - z[s]) : 1e10f;
        float a = 1.0f - expf(-d * fmaxf(sg[s], 0.0f));
        wgt[s] = a * T;
        T *= (1.0f - a + 1e-10f);
    }
    // pdf over w[1..10] (+1e-5)
    float wq[SS-2]; float sum = 0.0f;
    for (int i = 0; i < SS-2; i++) { wq[i] = wgt[i+1] + 1e-5f; sum += wq[i]; }
    float cdf[SS-1]; cdf[0] = 0.0f; float c = 0.0f;
    for (int i = 0; i < SS-2; i++) { c += wq[i] / sum; cdf[i+1] = c; }
    float bins[SS-1];
    for (int i = 0; i < SS-1; i++) bins[i] = 0.5f * (z[i] + z[i+1]);

    float ox = c2w[b*16 + 3], oy = c2w[b*16 + 7], oz = c2w[b*16 + 11];
    float dx = g_dirs[ray*3+0], dy = g_dirs[ray*3+1], dz = g_dirs[ray*3+2];

    for (int j = 0; j < SS; j++) {
        float u = jax_uniform(kq0, kq1, (uint32_t)(ray*SS + j));
        int ind = SS-1;  // searchsorted 'right': first i with cdf[i] > u, else 11
        for (int i = 0; i < SS-1; i++) { if (cdf[i] > u) { ind = i; break; } }
        int below = ind - 1; if (below < 0) below = 0; if (below > SS-2) below = SS-2;
        int above = (ind > SS-2) ? (SS-2) : ind;
        float clo = cdf[below], chi = cdf[above];
        float blo = bins[below], bhi = bins[above];
        float den = chi - clo; if (den < 1e-8f) den = 1.0f;
        float fz = blo + (u - clo) / den * (bhi - blo);
        g_finez[base + j] = fz;
        g_points_f[(base + j)*3 + 0] = ox + dx*fz;
        g_points_f[(base + j)*3 + 1] = oy + dy*fz;
        g_points_f[(base + j)*3 + 2] = oz + dz*fz;
    }
}

// ---------------- kernel 6: merge-sort + final integration ------------------
__global__ void final_kernel(float* __restrict__ out) {
    int ray = blockIdx.x * blockDim.x + threadIdx.x;
    if (ray >= NRAYS) return;
    int b = ray / HW, r = ray % HW;
    int h = r / IMG, w = r % IMG;
    int base = ray * SS;

    float z[2*SS]; float4 c[2*SS];
    const float4* rf = reinterpret_cast<const float4*>(g_rgbs_f);
    const float4* rc = reinterpret_cast<const float4*>(g_rgbs_c);
    for (int s = 0; s < SS; s++) { z[s]      = g_finez[base+s]; c[s]      = rf[base+s]; }
    for (int s = 0; s < SS; s++) { z[SS+s]   = g_zvals[base+s]; c[SS+s]   = rc[base+s]; }

    // stable insertion sort by z (fine entries precede coarse on ties)
    for (int i = 1; i < 2*SS; i++) {
        float kz = z[i]; float4 kc = c[i];
        int j = i - 1;
        while (j >= 0 && z[j] > kz) { z[j+1] = z[j]; c[j+1] = c[j]; j--; }
        z[j+1] = kz; c[j+1] = kc;
    }

    float T = 1.0f, R = 0.f, G = 0.f, Bc = 0.f, D = 0.f;
    for (int s = 0; s < 2*SS; s++) {
        float d = (s < 2*SS-1) ? (z[s+1] - z[s]) : 1e10f;
        float a = 1.0f - expf(-d * fmaxf(c[s].w, 0.0f));
        float wt = a * T;
        T *= (1.0f - a + 1e-10f);
        R += wt * c[s].x; G += wt * c[s].y; Bc += wt * c[s].z; D += wt * z[s];
    }
    // pixels: (B,3,H,W), *2-1
    out[((b*3 + 0)*IMG + h)*IMG + w] = R  * 2.0f - 1.0f;
    out[((b*3 + 1)*IMG + h)*IMG + w] = G  * 2.0f - 1.0f;
    out[((b*3 + 2)*IMG + h)*IMG + w] = Bc * 2.0f - 1.0f;
    // depth = D * (-rays_d_cam.z)
    float x = -1.0f + w * (2.0f/63.0f);
    float y =  1.0f - h * (2.0f/63.0f);
    float n = sqrtf(x*x + y*y + ZC*ZC);
    out[BB*3*HW + ray] = D * (-(ZC/n));
}

// ---------------- launch ----------------------------------------------------
extern "C" void kernel_launch(void* const* d_in, const int* in_sizes, int n_in,
                              void* d_out, int out_size) {
    const float* z    = (const float*)d_in[0];
    const float* c2w  = (const float*)d_in[1];
    const float* mw0  = (const float*)d_in[2];
    const float* mb0  = (const float*)d_in[3];
    const float* mw1  = (const float*)d_in[4];
    const float* mb1  = (const float*)d_in[5];
    const float* mw2  = (const float*)d_in[6];
    const float* mb2  = (const float*)d_in[7];
    const float* fw   = (const float*)d_in[8];
    const float* fb   = (const float*)d_in[9];
    const float* hw_  = (const float*)d_in[10];
    const float* hb   = (const float*)d_in[11];
    const float* ow   = (const float*)d_in[12];
    const float* ob   = (const float*)d_in[13];
    float* out = (float*)d_out;

    // JAX: key = key(42) -> data (0, 42); split (partitionable/foldlike):
    //   k_pert = threefry((0,42), counter (0,0)); k_pdf = threefry((0,42), (0,1))
    uint32_t kp0, kp1, kq0, kq1;
    { uint32_t x0 = 0u, x1 = 0u; tf2x32(0u, 42u, x0, x1); kp0 = x0; kp1 = x1; }
    { uint32_t x0 = 0u, x1 = 1u; tf2x32(0u, 42u, x0, x1); kq0 = x0; kq1 = x1; }

    size_t smem = (size_t)(2*128*AS_STRIDE + 3*128) * sizeof(float);  // ~136.7 KB
    cudaFuncSetAttribute(siren_kernel, cudaFuncAttributeMaxDynamicSharedMemorySize,
                         (int)smem);

    map_kernel   <<<BB, 256>>>(z, mw0, mb0, mw1, mb1, mw2, mb2);
    raygen_kernel<<<NRAYS/256, 256>>>(c2w, kp0, kp1);
    siren_kernel <<<NPTS/128, 256, smem>>>(0, fw, fb, hw_, hb, ow, ob);
    sample_kernel<<<NRAYS/256, 256>>>(c2w, kq0, kq1);
    siren_kernel <<<NPTS/128, 256, smem>>>(1, fw, fb, hw_, hb, ow, ob);
    final_kernel <<<NRAYS/256, 256>>>(out);
}

// round 5
// speedup vs baseline: 1.5502x; 1.5502x over previous
#include <cuda_runtime.h>
#include <cstdint>
#include <math.h>

// ---------------- problem constants (fixed by setup_inputs) ----------------
#define ZDIM 256
#define HID  128
#define NL   6
#define BB   2
#define IMG  64
#define HW   (IMG*IMG)          // 4096
#define SS   12
#define NRAYS (BB*HW)           // 8192
#define NPTS  (NRAYS*SS)        // 98304
#define FP_DIM (NL*HID)         // 768

#define MT    64                // points per block (M-tile)
#define AS_STRIDE 68            // 64 + 4 pad (activations, [n][m])
#define BS_STRIDE 132           // 128 + 4 pad (weights, [k][n])

// zc = -1/tan(deg2rad(12)/2), computed in double
#define ZC (-9.514364454222587f)

// ---------------- packed f32x2 helpers (sm_103a) ----------------------------
#define PACKF2(out, lo, hi) \
    asm("mov.b64 %0, {%1, %2};" : "=l"(out) : "f"(lo), "f"(hi))
#define UNPACKF2(lo, hi, in) \
    asm("mov.b64 {%0, %1}, %2;" : "=f"(lo), "=f"(hi) : "l"(in))
#define FMAF2(acc, a, b) \
    asm("fma.rn.f32x2 %0, %1, %2, %3;" : "=l"(acc) : "l"(a), "l"(b), "l"(acc))

// ---------------- device scratch (no allocations allowed) ------------------
__device__ float g_freqs[BB*FP_DIM];
__device__ float g_phases[BB*FP_DIM];
__device__ float g_points[NPTS*3];     // coarse world points
__device__ float g_zvals[NPTS];        // coarse z (with perturbation)
__device__ float g_dirs[NRAYS*3];      // world-space ray dirs
__device__ float g_rgbs_c[NPTS*4];     // coarse rgb+sigma
__device__ float g_finez[NPTS];        // fine z samples
__device__ float g_points_f[NPTS*3];   // fine world points
__device__ float g_rgbs_f[NPTS*4];     // fine rgb+sigma

// ---------------- Threefry-2x32-20 (matches JAX) ---------------------------
__host__ __device__ static inline void tf2x32(uint32_t k0, uint32_t k1,
                                              uint32_t& x0, uint32_t& x1) {
    uint32_t ks2 = k0 ^ k1 ^ 0x1BD11BDAu;
    x0 += k0; x1 += k1;
#define TF_RND(r) { x0 += x1; x1 = (x1 << (r)) | (x1 >> (32 - (r))); x1 ^= x0; }
    TF_RND(13) TF_RND(15) TF_RND(26) TF_RND(6)
    x0 += k1;  x1 += ks2 + 1u;
    TF_RND(17) TF_RND(29) TF_RND(16) TF_RND(24)
    x0 += ks2; x1 += k0 + 2u;
    TF_RND(13) TF_RND(15) TF_RND(26) TF_RND(6)
    x0 += k0;  x1 += k1 + 3u;
    TF_RND(17) TF_RND(29) TF_RND(16) TF_RND(24)
    x0 += k1;  x1 += ks2 + 4u;
    TF_RND(13) TF_RND(15) TF_RND(26) TF_RND(6)
    x0 += ks2; x1 += k0 + 5u;
#undef TF_RND
}

// JAX partitionable random bits: counter = 64-bit index (hi=0), bits = o0 ^ o1
__device__ static inline float jax_uniform(uint32_t k0, uint32_t k1, uint32_t idx) {
    uint32_t x0 = 0u, x1 = idx;
    tf2x32(k0, k1, x0, x1);
    uint32_t bits = x0 ^ x1;
    return __uint_as_float((bits >> 9) | 0x3f800000u) - 1.0f;
}

// ---------------- kernel 1: mapping network --------------------------------
__global__ void map_kernel(const float* __restrict__ z,
                           const float* __restrict__ w0, const float* __restrict__ b0,
                           const float* __restrict__ w1, const float* __restrict__ b1,
                           const float* __restrict__ w2, const float* __restrict__ b2) {
    __shared__ float sh[ZDIM];
    int b = blockIdx.x, t = threadIdx.x;
    sh[t] = z[b*ZDIM + t];
    __syncthreads();
    float acc = b0[t];
    for (int k = 0; k < ZDIM; k++) acc = fmaf(sh[k], w0[k*256 + t], acc);
    float v = (acc >= 0.f) ? acc : 0.2f*acc;
    __syncthreads(); sh[t] = v; __syncthreads();
    acc = b1[t];
    for (int k = 0; k < 256; k++) acc = fmaf(sh[k], w1[k*256 + t], acc);
    v = (acc >= 0.f) ? acc : 0.2f*acc;
    __syncthreads(); sh[t] = v; __syncthreads();
    for (int j = t; j < FP_DIM*2; j += 256) {
        float a = b2[j];
        for (int k = 0; k < 256; k++) a = fmaf(sh[k], w2[k*(FP_DIM*2) + j], a);
        if (j < FP_DIM) g_freqs[b*FP_DIM + j] = a*15.0f + 30.0f;
        else            g_phases[b*FP_DIM + (j - FP_DIM)] = a;
    }
}

// ---------------- kernel 2: ray generation + coarse points -----------------
__global__ void raygen_kernel(const float* __restrict__ c2w,
                              uint32_t kp0, uint32_t kp1) {
    int ray = blockIdx.x * blockDim.x + threadIdx.x;
    if (ray >= NRAYS) return;
    int b = ray / HW, r = ray % HW;
    int h = r / IMG, w = r % IMG;
    float x = -1.0f + w * (2.0f/63.0f);
    float y =  1.0f - h * (2.0f/63.0f);
    float n  = sqrtf(x*x + y*y + ZC*ZC);
    float dx = x/n, dy = y/n, dz = ZC/n;
    const float* M = c2w + b*16;
    g_dirs[ray*3+0] = M[0]*dx + M[1]*dy + M[2]*dz;
    g_dirs[ray*3+1] = M[4]*dx + M[5]*dy + M[6]*dz;
    g_dirs[ray*3+2] = M[8]*dx + M[9]*dy + M[10]*dz;
    const float spacing = (1.12f - 0.88f) / 11.0f;
    for (int s = 0; s < SS; s++) {
        int idx = ray*SS + s;
        float u   = jax_uniform(kp0, kp1, (uint32_t)idx);
        float off = (u - 0.5f) * spacing;
        float zv  = 0.88f + s*spacing + off;
        float px = dx*zv, py = dy*zv, pz = dz*zv;
        g_points[idx*3+0] = M[0]*px + M[1]*py + M[2]*pz  + M[3];
        g_points[idx*3+1] = M[4]*px + M[5]*py + M[6]*pz  + M[7];
        g_points[idx*3+2] = M[8]*px + M[9]*py + M[10]*pz + M[11];
        g_zvals[idx] = zv;
    }
}

// ---------------- kernel 3/5: fused SIREN forward ---------------------------
// M-tile = 64 points, 256 threads, 2 CTAs/SM.
// As: [n][m] activations (stride 68). Bs: [k][n] weights (stride 132).
// Thread (tx=tid&15, ty=tid>>4): 4 m-rows (ty*4+i), 8 n-cols (tx*4 + j, 64+tx*4 + j).
__global__ void __launch_bounds__(256, 2)
siren_kernel(int fine,
             const float* __restrict__ fw, const float* __restrict__ fb,
             const float* __restrict__ hw_, const float* __restrict__ hb,
             const float* __restrict__ ow, const float* __restrict__ ob) {
    extern __shared__ float sm[];
    float* As = sm;                          // [128][68]
    float* Bs = sm + 128*AS_STRIDE;          // [128][132]
    float* fr = sm + 128*AS_STRIDE + 128*BS_STRIDE;  // 128
    float* ph = fr + 128;                    // 128
    float* bi = ph + 128;                    // 128

    const float* pts  = fine ? g_points_f : g_points;
    float*       outr = fine ? g_rgbs_f   : g_rgbs_c;

    int tid = threadIdx.x;
    int tx = tid & 15, ty = tid >> 4;
    int m0 = blockIdx.x * MT;
    int batch = m0 / (HW*SS);
    const float* frq = g_freqs  + batch*FP_DIM;
    const float* phs = g_phases + batch*FP_DIM;

    // ---- first layer: 3 -> 128 ----
    {
        float* ptsh = Bs;           // 192
        float* fwsh = Bs + 256;     // 384
        float* fbsh = Bs + 768;     // 128
        for (int i = tid; i < MT*3; i += 256) ptsh[i] = pts[m0*3 + i];
        for (int i = tid; i < 384; i += 256) fwsh[i] = fw[i];
        if (tid < 128) { fbsh[tid] = fb[tid]; fr[tid] = frq[tid]; ph[tid] = phs[tid]; }
        __syncthreads();
#pragma unroll
        for (int j = 0; j < 8; j++) {
            int n = (j < 4) ? (tx*4 + j) : (64 + tx*4 + (j-4));
            float w0v = fwsh[n], w1v = fwsh[128+n], w2v = fwsh[256+n];
            float bn = fbsh[n], fn = fr[n], pn = ph[n];
#pragma unroll
            for (int i = 0; i < 4; i++) {
                int m = ty*4 + i;
                float v = bn + ptsh[m*3]*w0v + ptsh[m*3+1]*w1v + ptsh[m*3+2]*w2v;
                As[n*AS_STRIDE + m] = sinf(fn*v + pn);
            }
        }
        __syncthreads();
    }

    // ---- hidden layers 1..5: 128 -> 128 with sin(freq*(xW+b)+phase) ----
    for (int l = 1; l < NL; l++) {
        const float* W = hw_ + (l-1)*HID*HID;
        for (int i = tid*4; i < HID*HID; i += 1024) {
            int k = i >> 7, n = i & 127;
            float4 v = *reinterpret_cast<const float4*>(W + i);
            *reinterpret_cast<float4*>(&Bs[k*BS_STRIDE + n]) = v;
        }
        if (tid < 128) {
            fr[tid] = frq[l*HID + tid];
            ph[tid] = phs[l*HID + tid];
            bi[tid] = hb[(l-1)*HID + tid];
        }
        __syncthreads();

        // packed accumulators: acc[i][j2] = n-pair for m-row i
        unsigned long long acc[4][4];
#pragma unroll
        for (int i = 0; i < 4; i++)
#pragma unroll
            for (int j = 0; j < 4; j++) acc[i][j] = 0ull;

#pragma unroll 4
        for (int k = 0; k < HID; k++) {
            ulonglong2 b0 = *reinterpret_cast<const ulonglong2*>(&Bs[k*BS_STRIDE + tx*4]);
            ulonglong2 b1 = *reinterpret_cast<const ulonglong2*>(&Bs[k*BS_STRIDE + 64 + tx*4]);
            float4 a0 = *reinterpret_cast<const float4*>(&As[k*AS_STRIDE + ty*4]);
            float af[4] = {a0.x, a0.y, a0.z, a0.w};
            unsigned long long ad[4];
#pragma unroll
            for (int i = 0; i < 4; i++) PACKF2(ad[i], af[i], af[i]);
            unsigned long long bp[4] = {b0.x, b0.y, b1.x, b1.y};
#pragma unroll
            for (int i = 0; i < 4; i++)
#pragma unroll
                for (int j = 0; j < 4; j++) FMAF2(acc[i][j], ad[i], bp[j]);
        }
        __syncthreads();
#pragma unroll
        for (int j2 = 0; j2 < 4; j2++) {
            int nb = (j2 < 2) ? (tx*4 + j2*2) : (64 + tx*4 + (j2-2)*2);
            float f0 = fr[nb],   p0 = ph[nb],   c0 = bi[nb];
            float f1 = fr[nb+1], p1 = ph[nb+1], c1 = bi[nb+1];
#pragma unroll
            for (int i = 0; i < 4; i++) {
                float v0, v1;
                UNPACKF2(v0, v1, acc[i][j2]);
                int m = ty*4 + i;
                As[nb*AS_STRIDE + m]     = sinf(f0*(v0 + c0) + p0);
                As[(nb+1)*AS_STRIDE + m] = sinf(f1*(v1 + c1) + p1);
            }
        }
        __syncthreads();
    }

    // ---- output layer: 128 -> 4, sigmoid on rgb ----
    {
        float* owsh = Bs;          // 512
        float* obsh = Bs + 512;    // 4
        for (int i = tid; i < 512; i += 256) owsh[i] = ow[i];
        if (tid < 4) obsh[tid] = ob[tid];
        __syncthreads();
        int m = tid >> 2, j = tid & 3;   // 64 points x 4 outputs = 256 threads
        float a = obsh[j];
        for (int k = 0; k < HID; k++)
            a = fmaf(As[k*AS_STRIDE + m], owsh[k*4 + j], a);
        if (j < 3) a = 1.0f / (1.0f + expf(-a));
        outr[(m0 + m)*4 + j] = a;
    }
}

// ---------------- kernel 4: coarse integration + inverse-CDF sampling ------
__global__ void sample_kernel(const float* __restrict__ c2w,
                              uint32_t kq0, uint32_t kq1) {
    int ray = blockIdx.x * blockDim.x + threadIdx.x;
    if (ray >= NRAYS) return;
    int b = ray / HW;
    int base = ray * SS;

    float z[SS], sg[SS];
    for (int s = 0; s < SS; s++) {
        z[s]  = g_zvals[base + s];
        sg[s] = g_rgbs_c[(base + s)*4 + 3];
    }
    // fancy_integration weights
    float wgt[SS]; float T = 1.0f;
    for (int s = 0; s < SS; s++) {
        float d = (s < SS-1) ? (z[s+1] - z[s]) : 1e10f;
        float a = 1.0f - expf(-d * fmaxf(sg[s], 0.0f));
        wgt[s] = a * T;
        T *= (1.0f - a + 1e-10f);
    }
    // pdf over w[1..10] (+1e-5)
    float wq[SS-2]; float sum = 0.0f;
    for (int i = 0; i < SS-2; i++) { wq[i] = wgt[i+1] + 1e-5f; sum += wq[i]; }
    float cdf[SS-1]; cdf[0] = 0.0f; float c = 0.0f;
    for (int i = 0; i < SS-2; i++) { c += wq[i] / sum; cdf[i+1] = c; }
    float bins[SS-1];
    for (int i = 0; i < SS-1; i++) bins[i] = 0.5f * (z[i] + z[i+1]);

    float ox = c2w[b*16 + 3], oy = c2w[b*16 + 7], oz = c2w[b*16 + 11];
    float dx = g_dirs[ray*3+0], dy = g_dirs[ray*3+1], dz = g_dirs[ray*3+2];

    for (int j = 0; j < SS; j++) {
        float u = jax_uniform(kq0, kq1, (uint32_t)(ray*SS + j));
        int ind = SS-1;  // searchsorted 'right': first i with cdf[i] > u, else 11
        for (int i = 0; i < SS-1; i++) { if (cdf[i] > u) { ind = i; break; } }
        int below = ind - 1; if (below < 0) below = 0; if (below > SS-2) below = SS-2;
        int above = (ind > SS-2) ? (SS-2) : ind;
        float clo = cdf[below], chi = cdf[above];
        float blo = bins[below], bhi = bins[above];
        float den = chi - clo; if (den < 1e-8f) den = 1.0f;
        float fz = blo + (u - clo) / den * (bhi - blo);
        g_finez[base + j] = fz;
        g_points_f[(base + j)*3 + 0] = ox + dx*fz;
        g_points_f[(base + j)*3 + 1] = oy + dy*fz;
        g_points_f[(base + j)*3 + 2] = oz + dz*fz;
    }
}

// ---------------- kernel 6: merge-sort + final integration ------------------
__global__ void final_kernel(float* __restrict__ out) {
    int ray = blockIdx.x * blockDim.x + threadIdx.x;
    if (ray >= NRAYS) return;
    int b = ray / HW, r = ray % HW;
    int h = r / IMG, w = r % IMG;
    int base = ray * SS;

    float z[2*SS]; float4 c[2*SS];
    const float4* rf = reinterpret_cast<const float4*>(g_rgbs_f);
    const float4* rc = reinterpret_cast<const float4*>(g_rgbs_c);
    for (int s = 0; s < SS; s++) { z[s]      = g_finez[base+s]; c[s]      = rf[base+s]; }
    for (int s = 0; s < SS; s++) { z[SS+s]   = g_zvals[base+s]; c[SS+s]   = rc[base+s]; }

    // stable insertion sort by z (fine entries precede coarse on ties)
    for (int i = 1; i < 2*SS; i++) {
        float kz = z[i]; float4 kc = c[i];
        int j = i - 1;
        while (j >= 0 && z[j] > kz) { z[j+1] = z[j]; c[j+1] = c[j]; j--; }
        z[j+1] = kz; c[j+1] = kc;
    }

    float T = 1.0f, R = 0.f, G = 0.f, Bc = 0.f, D = 0.f;
    for (int s = 0; s < 2*SS; s++) {
        float d = (s < 2*SS-1) ? (z[s+1] - z[s]) : 1e10f;
        float a = 1.0f - expf(-d * fmaxf(c[s].w, 0.0f));
        float wt = a * T;
        T *= (1.0f - a + 1e-10f);
        R += wt * c[s].x; G += wt * c[s].y; Bc += wt * c[s].z; D += wt * z[s];
    }
    // pixels: (B,3,H,W), *2-1
    out[((b*3 + 0)*IMG + h)*IMG + w] = R  * 2.0f - 1.0f;
    out[((b*3 + 1)*IMG + h)*IMG + w] = G  * 2.0f - 1.0f;
    out[((b*3 + 2)*IMG + h)*IMG + w] = Bc * 2.0f - 1.0f;
    // depth = D * (-rays_d_cam.z)
    float x = -1.0f + w * (2.0f/63.0f);
    float y =  1.0f - h * (2.0f/63.0f);
    float n = sqrtf(x*x + y*y + ZC*ZC);
    out[BB*3*HW + ray] = D * (-(ZC/n));
}

// ---------------- launch ----------------------------------------------------
extern "C" void kernel_launch(void* const* d_in, const int* in_sizes, int n_in,
                              void* d_out, int out_size) {
    const float* z    = (const float*)d_in[0];
    const float* c2w  = (const float*)d_in[1];
    const float* mw0  = (const float*)d_in[2];
    const float* mb0  = (const float*)d_in[3];
    const float* mw1  = (const float*)d_in[4];
    const float* mb1  = (const float*)d_in[5];
    const float* mw2  = (const float*)d_in[6];
    const float* mb2  = (const float*)d_in[7];
    const float* fw   = (const float*)d_in[8];
    const float* fb   = (const float*)d_in[9];
    const float* hw_  = (const float*)d_in[10];
    const float* hb   = (const float*)d_in[11];
    const float* ow   = (const float*)d_in[12];
    const float* ob   = (const float*)d_in[13];
    float* out = (float*)d_out;

    // JAX: key = key(42) -> data (0, 42); split (partitionable):
    //   k_pert = threefry((0,42), (0,0)); k_pdf = threefry((0,42), (0,1))
    uint32_t kp0, kp1, kq0, kq1;
    { uint32_t x0 = 0u, x1 = 0u; tf2x32(0u, 42u, x0, x1); kp0 = x0; kp1 = x1; }
    { uint32_t x0 = 0u, x1 = 1u; tf2x32(0u, 42u, x0, x1); kq0 = x0; kq1 = x1; }

    size_t smem = (size_t)(128*AS_STRIDE + 128*BS_STRIDE + 3*128) * sizeof(float); // ~101.5 KB
    cudaFuncSetAttribute(siren_kernel, cudaFuncAttributeMaxDynamicSharedMemorySize,
                         (int)smem);

    map_kernel   <<<BB, 256>>>(z, mw0, mb0, mw1, mb1, mw2, mb2);
    raygen_kernel<<<NRAYS/256, 256>>>(c2w, kp0, kp1);
    siren_kernel <<<NPTS/MT, 256, smem>>>(0, fw, fb, hw_, hb, ow, ob);
    sample_kernel<<<NRAYS/256, 256>>>(c2w, kq0, kq1);
    siren_kernel <<<NPTS/MT, 256, smem>>>(1, fw, fb, hw_, hb, ow, ob);
    final_kernel <<<NRAYS/256, 256>>>(out);
}

// round 6
// speedup vs baseline: 1.8306x; 1.1809x over previous
#include <cuda_runtime.h>
#include <cstdint>
#include <math.h>

// ---------------- problem constants (fixed by setup_inputs) ----------------
#define ZDIM 256
#define HID  128
#define NL   6
#define BB   2
#define IMG  64
#define HW   (IMG*IMG)          // 4096
#define SS   12
#define NRAYS (BB*HW)           // 8192
#define NPTS  (NRAYS*SS)        // 98304
#define FP_DIM (NL*HID)         // 768

#define MT    64                // points per block (M-tile)

// zc = -1/tan(deg2rad(12)/2), computed in double
#define ZC (-9.514364454222587f)

// ---------------- packed f32x2 helpers (sm_103a) ----------------------------
#define PACKF2(out, lo, hi) \
    asm("mov.b64 %0, {%1, %2};" : "=l"(out) : "f"(lo), "f"(hi))
#define UNPACKF2(lo, hi, in) \
    asm("mov.b64 {%0, %1}, %2;" : "=f"(lo), "=f"(hi) : "l"(in))
#define FMAF2(acc, a, b) \
    asm("fma.rn.f32x2 %0, %1, %2, %3;" : "=l"(acc) : "l"(a), "l"(b), "l"(acc))

// ---------------- cp.async helpers ------------------------------------------
__device__ __forceinline__ void cp16(void* smem, const void* gmem) {
    uint32_t s = (uint32_t)__cvta_generic_to_shared(smem);
    asm volatile("cp.async.cg.shared.global [%0], [%1], 16;" :: "r"(s), "l"(gmem));
}
#define CP_COMMIT() asm volatile("cp.async.commit_group;")
#define CP_WAIT0()  asm volatile("cp.async.wait_group 0;")

// ---------------- fast branch-free sin (Cody-Waite + deg-7 odd minimax) ----
// |x| <= ~200 here; n <= ~64 so 3-term reduction error ~1e-9. Accuracy ~1 ulp
// on the reduced range — same class as library sinf.
__device__ __forceinline__ float fast_sin(float x) {
    const float INVPI = 0.3183098861837907f;
    float fn = rintf(x * INVPI);
    int n = (int)fn;
    float r = fmaf(fn, -3.140625f, x);
    r = fmaf(fn, -9.67502593994140625e-4f, r);
    r = fmaf(fn, -1.50995799097838e-7f, r);
    float s = r * r;
    float p = fmaf(s, -1.9515295891e-4f, 8.3321608736e-3f);
    p = fmaf(s, p, -1.6666654611e-1f);
    float y = fmaf(r * s, p, r);
    // sin(x) = (-1)^n * sin(r)
    return (n & 1) ? -y : y;
}

// ---------------- device scratch (no allocations allowed) ------------------
__device__ float g_freqs[BB*FP_DIM];
__device__ float g_phases[BB*FP_DIM];
__device__ float g_points[NPTS*3];     // coarse world points
__device__ float g_zvals[NPTS];        // coarse z (with perturbation)
__device__ float g_dirs[NRAYS*3];      // world-space ray dirs
__device__ float g_rgbs_c[NPTS*4];     // coarse rgb+sigma
__device__ float g_finez[NPTS];        // fine z samples
__device__ float g_points_f[NPTS*3];   // fine world points
__device__ float g_rgbs_f[NPTS*4];     // fine rgb+sigma

// ---------------- Threefry-2x32-20 (matches JAX) ---------------------------
__host__ __device__ static inline void tf2x32(uint32_t k0, uint32_t k1,
                                              uint32_t& x0, uint32_t& x1) {
    uint32_t ks2 = k0 ^ k1 ^ 0x1BD11BDAu;
    x0 += k0; x1 += k1;
#define TF_RND(r) { x0 += x1; x1 = (x1 << (r)) | (x1 >> (32 - (r))); x1 ^= x0; }
    TF_RND(13) TF_RND(15) TF_RND(26) TF_RND(6)
    x0 += k1;  x1 += ks2 + 1u;
    TF_RND(17) TF_RND(29) TF_RND(16) TF_RND(24)
    x0 += ks2; x1 += k0 + 2u;
    TF_RND(13) TF_RND(15) TF_RND(26) TF_RND(6)
    x0 += k0;  x1 += k1 + 3u;
    TF_RND(17) TF_RND(29) TF_RND(16) TF_RND(24)
    x0 += k1;  x1 += ks2 + 4u;
    TF_RND(13) TF_RND(15) TF_RND(26) TF_RND(6)
    x0 += ks2; x1 += k0 + 5u;
#undef TF_RND
}

__device__ static inline float jax_uniform(uint32_t k0, uint32_t k1, uint32_t idx) {
    uint32_t x0 = 0u, x1 = idx;
    tf2x32(k0, k1, x0, x1);
    uint32_t bits = x0 ^ x1;
    return __uint_as_float((bits >> 9) | 0x3f800000u) - 1.0f;
}

// ---------------- kernel 1: mapping network --------------------------------
__global__ void map_kernel(const float* __restrict__ z,
                           const float* __restrict__ w0, const float* __restrict__ b0,
                           const float* __restrict__ w1, const float* __restrict__ b1,
                           const float* __restrict__ w2, const float* __restrict__ b2) {
    __shared__ float sh[ZDIM];
    int b = blockIdx.x, t = threadIdx.x;
    sh[t] = z[b*ZDIM + t];
    __syncthreads();
    float acc = b0[t];
    for (int k = 0; k < ZDIM; k++) acc = fmaf(sh[k], w0[k*256 + t], acc);
    float v = (acc >= 0.f) ? acc : 0.2f*acc;
    __syncthreads(); sh[t] = v; __syncthreads();
    acc = b1[t];
    for (int k = 0; k < 256; k++) acc = fmaf(sh[k], w1[k*256 + t], acc);
    v = (acc >= 0.f) ? acc : 0.2f*acc;
    __syncthreads(); sh[t] = v; __syncthreads();
    for (int j = t; j < FP_DIM*2; j += 256) {
        float a = b2[j];
        for (int k = 0; k < 256; k++) a = fmaf(sh[k], w2[k*(FP_DIM*2) + j], a);
        if (j < FP_DIM) g_freqs[b*FP_DIM + j] = a*15.0f + 30.0f;
        else            g_phases[b*FP_DIM + (j - FP_DIM)] = a;
    }
}

// ---------------- kernel 2: ray generation + coarse points -----------------
__global__ void raygen_kernel(const float* __restrict__ c2w,
                              uint32_t kp0, uint32_t kp1) {
    int ray = blockIdx.x * blockDim.x + threadIdx.x;
    if (ray >= NRAYS) return;
    int b = ray / HW, r = ray % HW;
    int h = r / IMG, w = r % IMG;
    float x = -1.0f + w * (2.0f/63.0f);
    float y =  1.0f - h * (2.0f/63.0f);
    float n  = sqrtf(x*x + y*y + ZC*ZC);
    float dx = x/n, dy = y/n, dz = ZC/n;
    const float* M = c2w + b*16;
    g_dirs[ray*3+0] = M[0]*dx + M[1]*dy + M[2]*dz;
    g_dirs[ray*3+1] = M[4]*dx + M[5]*dy + M[6]*dz;
    g_dirs[ray*3+2] = M[8]*dx + M[9]*dy + M[10]*dz;
    const float spacing = (1.12f - 0.88f) / 11.0f;
    for (int s = 0; s < SS; s++) {
        int idx = ray*SS + s;
        float u   = jax_uniform(kp0, kp1, (uint32_t)idx);
        float off = (u - 0.5f) * spacing;
        float zv  = 0.88f + s*spacing + off;
        float px = dx*zv, py = dy*zv, pz = dz*zv;
        g_points[idx*3+0] = M[0]*px + M[1]*py + M[2]*pz  + M[3];
        g_points[idx*3+1] = M[4]*px + M[5]*py + M[6]*pz  + M[7];
        g_points[idx*3+2] = M[8]*px + M[9]*py + M[10]*pz + M[11];
        g_zvals[idx] = zv;
    }
}

// ---------------- kernel 3/5: fused SIREN forward ---------------------------
// MT=64 pts/block, 256 threads, 2 CTAs/SM.
// As: [n][m-swizzled] 128x64 floats, group-of-4 XOR swizzle: element (n, m)
//     lives at As[n*64 + (((m>>2) ^ (n&15))<<2) + (m&3)].
// Bs: [k][n] 128x128 floats (no pad; whole-row reads are conflict-free).
// cp.async prefetch of next layer's weights overlaps the sin epilogue.
__global__ void __launch_bounds__(256, 2)
siren_kernel(int fine,
             const float* __restrict__ fw, const float* __restrict__ fb,
             const float* __restrict__ hw_, const float* __restrict__ hb,
             const float* __restrict__ ow, const float* __restrict__ ob) {
    extern __shared__ float smem_[];
    float* As = smem_;                 // 8192 floats (32 KB)
    float* Bs = smem_ + 8192;          // 16384 floats (64 KB)
    float* fr = Bs + 16384;            // 768
    float* ph = fr + 768;              // 768
    float* bi = ph + 768;              // 640
    float* sc = bi + 640;              // 708 scratch: pts 192 | fw 384 | fb 128 | ob 4

    const float* pts  = fine ? g_points_f : g_points;
    float*       outr = fine ? g_rgbs_f   : g_rgbs_c;

    int tid = threadIdx.x;
    int tx = tid & 15, ty = tid >> 4;
    int m0 = blockIdx.x * MT;
    int batch = m0 / (HW*SS);

    // ---- prologue: prefetch layer-1 weights; load fpb + first-layer scratch
    for (int i = tid; i < 4096; i += 256) cp16(&Bs[i*4], hw_ + i*4);
    CP_COMMIT();
    {
        const float* frq = g_freqs  + batch*FP_DIM;
        const float* phs = g_phases + batch*FP_DIM;
        for (int i = tid; i < FP_DIM; i += 256) { fr[i] = frq[i]; ph[i] = phs[i]; }
        for (int i = tid; i < (NL-1)*HID; i += 256) bi[i] = hb[i];
        for (int i = tid; i < MT*3; i += 256) sc[i] = pts[m0*3 + i];
        for (int i = tid; i < 384; i += 256) sc[192 + i] = fw[i];
        if (tid < 128) sc[576 + tid] = fb[tid];
        if (tid < 4)   sc[704 + tid] = ob[tid];
    }
    __syncthreads();

    // ---- first layer: 3 -> 128 (reads scratch only; W1 cp.async in flight)
    {
#pragma unroll
        for (int j = 0; j < 8; j++) {
            int n = (j < 4) ? (tx*4 + j) : (64 + tx*4 + (j-4));
            float w0v = sc[192 + n], w1v = sc[192 + 128 + n], w2v = sc[192 + 256 + n];
            float bn = sc[576 + n], fn = fr[n], pn = ph[n];
            float v4[4];
#pragma unroll
            for (int i = 0; i < 4; i++) {
                int m = ty*4 + i;
                float v = bn + sc[m*3]*w0v + sc[m*3+1]*w1v + sc[m*3+2]*w2v;
                v4[i] = fast_sin(fn*v + pn);
            }
            *reinterpret_cast<float4*>(&As[n*64 + ((ty ^ (n & 15)) << 2)]) =
                make_float4(v4[0], v4[1], v4[2], v4[3]);
        }
    }
    CP_WAIT0();
    __syncthreads();

    // ---- hidden layers 1..5 ----
    for (int l = 1; l < NL; l++) {
        // mainloop: acc[i][j2] = packed n-pair for m-row i
        unsigned long long acc[4][4];
#pragma unroll
        for (int i = 0; i < 4; i++)
#pragma unroll
            for (int j = 0; j < 4; j++) acc[i][j] = 0ull;

#pragma unroll 4
        for (int k = 0; k < HID; k++) {
            ulonglong2 b0 = *reinterpret_cast<const ulonglong2*>(&Bs[k*128 + tx*4]);
            ulonglong2 b1 = *reinterpret_cast<const ulonglong2*>(&Bs[k*128 + 64 + tx*4]);
            float4 a0 = *reinterpret_cast<const float4*>(&As[k*64 + ((ty ^ (k & 15)) << 2)]);
            float af[4] = {a0.x, a0.y, a0.z, a0.w};
            unsigned long long ad[4];
#pragma unroll
            for (int i = 0; i < 4; i++) PACKF2(ad[i], af[i], af[i]);
            unsigned long long bp[4] = {b0.x, b0.y, b1.x, b1.y};
#pragma unroll
            for (int i = 0; i < 4; i++)
#pragma unroll
                for (int j = 0; j < 4; j++) FMAF2(acc[i][j], ad[i], bp[j]);
        }
        __syncthreads();   // all Bs reads + As reads done

        // prefetch next layer's weights (or output weights) into Bs
        if (l < NL-1) {
            const float* Wn = hw_ + l*HID*HID;
            for (int i = tid; i < 4096; i += 256) cp16(&Bs[i*4], Wn + i*4);
        } else {
            if (tid < 128) cp16(&Bs[tid*4], ow + tid*4);
        }
        CP_COMMIT();

        // epilogue: sin + swizzled transposed store (overlaps cp.async)
#pragma unroll
        for (int j2 = 0; j2 < 4; j2++) {
            int nb = (j2 < 2) ? (tx*4 + j2*2) : (64 + tx*4 + (j2-2)*2);
            float f0 = fr[l*HID + nb],   p0 = ph[l*HID + nb],   c0 = bi[(l-1)*HID + nb];
            float f1 = fr[l*HID + nb+1], p1 = ph[l*HID + nb+1], c1 = bi[(l-1)*HID + nb+1];
            float v0[4], v1[4];
#pragma unroll
            for (int i = 0; i < 4; i++) {
                float a0, a1;
                UNPACKF2(a0, a1, acc[i][j2]);
                v0[i] = fast_sin(f0*(a0 + c0) + p0);
                v1[i] = fast_sin(f1*(a1 + c1) + p1);
            }
            *reinterpret_cast<float4*>(&As[nb*64 + ((ty ^ (nb & 15)) << 2)]) =
                make_float4(v0[0], v0[1], v0[2], v0[3]);
            *reinterpret_cast<float4*>(&As[(nb+1)*64 + ((ty ^ ((nb+1) & 15)) << 2)]) =
                make_float4(v1[0], v1[1], v1[2], v1[3]);
        }
        CP_WAIT0();
        __syncthreads();
    }

    // ---- output layer: 128 -> 4, sigmoid on rgb (ow resident in Bs[0..511])
    {
        int m = tid >> 2, j = tid & 3;   // 64 points x 4 outputs
        int mg = m >> 2, mc = m & 3;
        float a = sc[704 + j];
        for (int k = 0; k < HID; k++)
            a = fmaf(As[k*64 + (((mg ^ (k & 15)) << 2) | mc)], Bs[k*4 + j], a);
        if (j < 3) a = 1.0f / (1.0f + expf(-a));
        outr[(m0 + m)*4 + j] = a;
    }
}

// ---------------- kernel 4: coarse integration + inverse-CDF sampling ------
__global__ void sample_kernel(const float* __restrict__ c2w,
                              uint32_t kq0, uint32_t kq1) {
    int ray = blockIdx.x * blockDim.x + threadIdx.x;
    if (ray >= NRAYS) return;
    int b = ray / HW;
    int base = ray * SS;

    float z[SS], sg[SS];
    for (int s = 0; s < SS; s++) {
        z[s]  = g_zvals[base + s];
        sg[s] = g_rgbs_c[(base + s)*4 + 3];
    }
    float wgt[SS]; float T = 1.0f;
    for (int s = 0; s < SS; s++) {
        float d = (s < SS-1) ? (z[s+1] - z[s]) : 1e10f;
        float a = 1.0f - expf(-d * fmaxf(sg[s], 0.0f));
        wgt[s] = a * T;
        T *= (1.0f - a + 1e-10f);
    }
    float wq[SS-2]; float sum = 0.0f;
    for (int i = 0; i < SS-2; i++) { wq[i] = wgt[i+1] + 1e-5f; sum += wq[i]; }
    float cdf[SS-1]; cdf[0] = 0.0f; float c = 0.0f;
    for (int i = 0; i < SS-2; i++) { c += wq[i] / sum; cdf[i+1] = c; }
    float bins[SS-1];
    for (int i = 0; i < SS-1; i++) bins[i] = 0.5f * (z[i] + z[i+1]);

    float ox = c2w[b*16 + 3], oy = c2w[b*16 + 7], oz = c2w[b*16 + 11];
    float dx = g_dirs[ray*3+0], dy = g_dirs[ray*3+1], dz = g_dirs[ray*3+2];

    for (int j = 0; j < SS; j++) {
        float u = jax_uniform(kq0, kq1, (uint32_t)(ray*SS + j));
        int ind = SS-1;
        for (int i = 0; i < SS-1; i++) { if (cdf[i] > u) { ind = i; break; } }
        int below = ind - 1; if (below < 0) below = 0; if (below > SS-2) below = SS-2;
        int above = (ind > SS-2) ? (SS-2) : ind;
        float clo = cdf[below], chi = cdf[above];
        float blo = bins[below], bhi = bins[above];
        float den = chi - clo; if (den < 1e-8f) den = 1.0f;
        float fz = blo + (u - clo) / den * (bhi - blo);
        g_finez[base + j] = fz;
        g_points_f[(base + j)*3 + 0] = ox + dx*fz;
        g_points_f[(base + j)*3 + 1] = oy + dy*fz;
        g_points_f[(base + j)*3 + 2] = oz + dz*fz;
    }
}

// ---------------- kernel 6: merge-sort + final integration ------------------
__global__ void final_kernel(float* __restrict__ out) {
    int ray = blockIdx.x * blockDim.x + threadIdx.x;
    if (ray >= NRAYS) return;
    int b = ray / HW, r = ray % HW;
    int h = r / IMG, w = r % IMG;
    int base = ray * SS;

    float z[2*SS]; float4 c[2*SS];
    const float4* rf = reinterpret_cast<const float4*>(g_rgbs_f);
    const float4* rc = reinterpret_cast<const float4*>(g_rgbs_c);
    for (int s = 0; s < SS; s++) { z[s]      = g_finez[base+s]; c[s]      = rf[base+s]; }
    for (int s = 0; s < SS; s++) { z[SS+s]   = g_zvals[base+s]; c[SS+s]   = rc[base+s]; }

    for (int i = 1; i < 2*SS; i++) {
        float kz = z[i]; float4 kc = c[i];
        int j = i - 1;
        while (j >= 0 && z[j] > kz) { z[j+1] = z[j]; c[j+1] = c[j]; j--; }
        z[j+1] = kz; c[j+1] = kc;
    }

    float T = 1.0f, R = 0.f, G = 0.f, Bc = 0.f, D = 0.f;
    for (int s = 0; s < 2*SS; s++) {
        float d = (s < 2*SS-1) ? (z[s+1] - z[s]) : 1e10f;
        float a = 1.0f - expf(-d * fmaxf(c[s].w, 0.0f));
        float wt = a * T;
        T *= (1.0f - a + 1e-10f);
        R += wt * c[s].x; G += wt * c[s].y; Bc += wt * c[s].z; D += wt * z[s];
    }
    out[((b*3 + 0)*IMG + h)*IMG + w] = R  * 2.0f - 1.0f;
    out[((b*3 + 1)*IMG + h)*IMG + w] = G  * 2.0f - 1.0f;
    out[((b*3 + 2)*IMG + h)*IMG + w] = Bc * 2.0f - 1.0f;
    float x = -1.0f + w * (2.0f/63.0f);
    float y =  1.0f - h * (2.0f/63.0f);
    float n = sqrtf(x*x + y*y + ZC*ZC);
    out[BB*3*HW + ray] = D * (-(ZC/n));
}

// ---------------- launch ----------------------------------------------------
extern "C" void kernel_launch(void* const* d_in, const int* in_sizes, int n_in,
                              void* d_out, int out_size) {
    const float* z    = (const float*)d_in[0];
    const float* c2w  = (const float*)d_in[1];
    const float* mw0  = (const float*)d_in[2];
    const float* mb0  = (const float*)d_in[3];
    const float* mw1  = (const float*)d_in[4];
    const float* mb1  = (const float*)d_in[5];
    const float* mw2  = (const float*)d_in[6];
    const float* mb2  = (const float*)d_in[7];
    const float* fw   = (const float*)d_in[8];
    const float* fb   = (const float*)d_in[9];
    const float* hw_  = (const float*)d_in[10];
    const float* hb   = (const float*)d_in[11];
    const float* ow   = (const float*)d_in[12];
    const float* ob   = (const float*)d_in[13];
    float* out = (float*)d_out;

    uint32_t kp0, kp1, kq0, kq1;
    { uint32_t x0 = 0u, x1 = 0u; tf2x32(0u, 42u, x0, x1); kp0 = x0; kp1 = x1; }
    { uint32_t x0 = 0u, x1 = 1u; tf2x32(0u, 42u, x0, x1); kq0 = x0; kq1 = x1; }

    // As 8192 + Bs 16384 + fr 768 + ph 768 + bi 640 + sc 708 = 27460 floats
    size_t smem = 27460 * sizeof(float);   // ~107.3 KB -> 2 CTAs/SM
    cudaFuncSetAttribute(siren_kernel, cudaFuncAttributeMaxDynamicSharedMemorySize,
                         (int)smem);

    map_kernel   <<<BB, 256>>>(z, mw0, mb0, mw1, mb1, mw2, mb2);
    raygen_kernel<<<NRAYS/256, 256>>>(c2w, kp0, kp1);
    siren_kernel <<<NPTS/MT, 256, smem>>>(0, fw, fb, hw_, hb, ow, ob);
    sample_kernel<<<NRAYS/256, 256>>>(c2w, kq0, kq1);
    siren_kernel <<<NPTS/MT, 256, smem>>>(1, fw, fb, hw_, hb, ow, ob);
    final_kernel <<<NRAYS/256, 256>>>(out);
}

// round 8
// speedup vs baseline: 2.2616x; 1.2354x over previous
#include <cuda_runtime.h>
#include <cuda_bf16.h>
#include <cstdint>
#include <math.h>

// ---------------- problem constants ----------------------------------------
#define ZDIM 256
#define HID  128
#define NL   6
#define BB   2
#define IMG  64
#define HW   (IMG*IMG)          // 4096
#define SS   12
#define NRAYS (BB*HW)           // 8192
#define NPTS  (NRAYS*SS)        // 98304
#define FP_DIM (NL*HID)         // 768
#define MT    128               // points per block

#define ZC (-9.514364454222587f)

// weight tile: n-major (row = n, 128 k bf16 + pad), stride 272B
#define WROW  272
#define BSPL  (128*WROW)        // 34816 bytes per split
#define BBUF  (3*BSPL)          // 104448 bytes per layer (3 splits)

// ---------------- smem layout (bytes) ---------------------------------------
#define SM_B    0               // 2 x BBUF = 208896
#define SM_PTS  208896          // 384 floats
#define SM_FR   210432          // 768 floats
#define SM_PH   213504          // 768 floats
#define SM_BI   216576          // 640 floats
#define SM_FW   219136          // 384 floats
#define SM_FB   220672          // 128 floats
#define SM_OW   221184          // 512 floats
#define SM_OB   223232          // 4 floats
#define SM_TOTAL 223264

// ---------------- PTX helpers -----------------------------------------------
__device__ __forceinline__ uint32_t smem_u32(const void* p) {
    uint32_t a;
    asm("{ .reg .u64 t; cvta.to.shared.u64 t, %1; cvt.u32.u64 %0, t; }"
        : "=r"(a) : "l"(p));
    return a;
}
__device__ __forceinline__ void cp16(void* smem, const void* gmem) {
    uint32_t s = (uint32_t)__cvta_generic_to_shared(smem);
    asm volatile("cp.async.cg.shared.global [%0], [%1], 16;" :: "r"(s), "l"(gmem));
}
#define CP_COMMIT() asm volatile("cp.async.commit_group;")
#define CP_WAIT0()  asm volatile("cp.async.wait_group 0;")

#define LDMX4(r0, r1, r2, r3, addr) \
    asm volatile("ldmatrix.sync.aligned.m8n8.x4.shared.b16 {%0,%1,%2,%3}, [%4];" \
        : "=r"(r0), "=r"(r1), "=r"(r2), "=r"(r3) : "r"(addr))

#define MMA4(c, a0, a1, a2, a3, b0, b1) \
    asm volatile("mma.sync.aligned.m16n8k16.row.col.f32.bf16.bf16.f32 " \
        "{%0,%1,%2,%3}, {%4,%5,%6,%7}, {%8,%9}, {%0,%1,%2,%3};" \
        : "+f"((c)[0]), "+f"((c)[1]), "+f"((c)[2]), "+f"((c)[3]) \
        : "r"(a0), "r"(a1), "r"(a2), "r"(a3), "r"(b0), "r"(b1))

// ---------------- fast branch-free sin (verified round 6) -------------------
__device__ __forceinline__ float fast_sin(float x) {
    const float INVPI = 0.3183098861837907f;
    float fn = rintf(x * INVPI);
    int n = (int)fn;
    float r = fmaf(fn, -3.140625f, x);
    r = fmaf(fn, -9.67502593994140625e-4f, r);
    r = fmaf(fn, -1.50995799097838e-7f, r);
    float s = r * r;
    float p = fmaf(s, -1.9515295891e-4f, 8.3321608736e-3f);
    p = fmaf(s, p, -1.6666654611e-1f);
    float y = fmaf(r * s, p, r);
    return (n & 1) ? -y : y;
}

// 3-way bf16 split of a float pair, packed for mma A operands (lo = even k)
__device__ __forceinline__ void pack3(float x, float y,
                                      uint32_t& p0, uint32_t& p1, uint32_t& p2) {
    __nv_bfloat162 h0 = __floats2bfloat162_rn(x, y);
    float2 g0 = __bfloat1622float2(h0);
    float rx = x - g0.x, ry = y - g0.y;
    __nv_bfloat162 h1 = __floats2bfloat162_rn(rx, ry);
    float2 g1 = __bfloat1622float2(h1);
    __nv_bfloat162 h2 = __floats2bfloat162_rn(rx - g1.x, ry - g1.y);
    p0 = *reinterpret_cast<uint32_t*>(&h0);
    p1 = *reinterpret_cast<uint32_t*>(&h1);
    p2 = *reinterpret_cast<uint32_t*>(&h2);
}

// ---------------- device scratch ---------------------------------------------
__device__ float g_freqs[BB*FP_DIM];
__device__ float g_phases[BB*FP_DIM];
__device__ float g_points[NPTS*3];
__device__ float g_zvals[NPTS];
__device__ float g_dirs[NRAYS*3];
__device__ float g_rgbs_c[NPTS*4];
__device__ float g_finez[NPTS];
__device__ float g_points_f[NPTS*3];
__device__ float g_rgbs_f[NPTS*4];
// pre-split hidden weights: 5 layers x (3 splits x 128 n-rows x 272B)
__device__ __align__(16) char g_wsplit[5*BBUF];

// ---------------- Threefry-2x32-20 (matches JAX) ----------------------------
__host__ __device__ static inline void tf2x32(uint32_t k0, uint32_t k1,
                                              uint32_t& x0, uint32_t& x1) {
    uint32_t ks2 = k0 ^ k1 ^ 0x1BD11BDAu;
    x0 += k0; x1 += k1;
#define TF_RND(r) { x0 += x1; x1 = (x1 << (r)) | (x1 >> (32 - (r))); x1 ^= x0; }
    TF_RND(13) TF_RND(15) TF_RND(26) TF_RND(6)
    x0 += k1;  x1 += ks2 + 1u;
    TF_RND(17) TF_RND(29) TF_RND(16) TF_RND(24)
    x0 += ks2; x1 += k0 + 2u;
    TF_RND(13) TF_RND(15) TF_RND(26) TF_RND(6)
    x0 += k0;  x1 += k1 + 3u;
    TF_RND(17) TF_RND(29) TF_RND(16) TF_RND(24)
    x0 += k1;  x1 += ks2 + 4u;
    TF_RND(13) TF_RND(15) TF_RND(26) TF_RND(6)
    x0 += ks2; x1 += k0 + 5u;
#undef TF_RND
}
__device__ static inline float jax_uniform(uint32_t k0, uint32_t k1, uint32_t idx) {
    uint32_t x0 = 0u, x1 = idx;
    tf2x32(k0, k1, x0, x1);
    uint32_t bits = x0 ^ x1;
    return __uint_as_float((bits >> 9) | 0x3f800000u) - 1.0f;
}

// ---------------- kernel 0: weight split + transpose pre-pass ----------------
__global__ void wsplit_kernel(const float* __restrict__ hw_) {
    int idx = blockIdx.x * 256 + threadIdx.x;
    if (idx >= 5*HID*HID) return;
    int l = idx / (HID*HID), r = idx % (HID*HID);
    int k = r >> 7, n = r & 127;
    float w = hw_[l*HID*HID + k*HID + n];
    __nv_bfloat16 b0 = __float2bfloat16(w);
    float r1 = w - __bfloat162float(b0);
    __nv_bfloat16 b1 = __float2bfloat16(r1);
    float r2 = r1 - __bfloat162float(b1);
    __nv_bfloat16 b2 = __float2bfloat16(r2);
    // n-major: row n holds k 0..127
    int off = n*WROW + k*2;
    char* base = g_wsplit + l*BBUF;
    *(__nv_bfloat16*)(base + off)          = b0;
    *(__nv_bfloat16*)(base + BSPL + off)   = b1;
    *(__nv_bfloat16*)(base + 2*BSPL + off) = b2;
}

// ---------------- kernel 1: mapping network ---------------------------------
__global__ void map_kernel(const float* __restrict__ z,
                           const float* __restrict__ w0, const float* __restrict__ b0,
                           const float* __restrict__ w1, const float* __restrict__ b1,
                           const float* __restrict__ w2, const float* __restrict__ b2) {
    __shared__ float sh[ZDIM];
    int b = blockIdx.x, t = threadIdx.x;
    sh[t] = z[b*ZDIM + t];
    __syncthreads();
    float acc = b0[t];
    for (int k = 0; k < ZDIM; k++) acc = fmaf(sh[k], w0[k*256 + t], acc);
    float v = (acc >= 0.f) ? acc : 0.2f*acc;
    __syncthreads(); sh[t] = v; __syncthreads();
    acc = b1[t];
    for (int k = 0; k < 256; k++) acc = fmaf(sh[k], w1[k*256 + t], acc);
    v = (acc >= 0.f) ? acc : 0.2f*acc;
    __syncthreads(); sh[t] = v; __syncthreads();
    for (int j = t; j < FP_DIM*2; j += 256) {
        float a = b2[j];
        for (int k = 0; k < 256; k++) a = fmaf(sh[k], w2[k*(FP_DIM*2) + j], a);
        if (j < FP_DIM) g_freqs[b*FP_DIM + j] = a*15.0f + 30.0f;
        else            g_phases[b*FP_DIM + (j - FP_DIM)] = a;
    }
}

// ---------------- kernel 2: ray generation ----------------------------------
__global__ void raygen_kernel(const float* __restrict__ c2w,
                              uint32_t kp0, uint32_t kp1) {
    int ray = blockIdx.x * blockDim.x + threadIdx.x;
    if (ray >= NRAYS) return;
    int b = ray / HW, r = ray % HW;
    int h = r / IMG, w = r % IMG;
    float x = -1.0f + w * (2.0f/63.0f);
    float y =  1.0f - h * (2.0f/63.0f);
    float n  = sqrtf(x*x + y*y + ZC*ZC);
    float dx = x/n, dy = y/n, dz = ZC/n;
    const float* M = c2w + b*16;
    g_dirs[ray*3+0] = M[0]*dx + M[1]*dy + M[2]*dz;
    g_dirs[ray*3+1] = M[4]*dx + M[5]*dy + M[6]*dz;
    g_dirs[ray*3+2] = M[8]*dx + M[9]*dy + M[10]*dz;
    const float spacing = (1.12f - 0.88f) / 11.0f;
    for (int s = 0; s < SS; s++) {
        int idx = ray*SS + s;
        float u   = jax_uniform(kp0, kp1, (uint32_t)idx);
        float off = (u - 0.5f) * spacing;
        float zv  = 0.88f + s*spacing + off;
        float px = dx*zv, py = dy*zv, pz = dz*zv;
        g_points[idx*3+0] = M[0]*px + M[1]*py + M[2]*pz  + M[3];
        g_points[idx*3+1] = M[4]*px + M[5]*py + M[6]*pz  + M[7];
        g_points[idx*3+2] = M[8]*px + M[9]*py + M[10]*pz + M[11];
        g_zvals[idx] = zv;
    }
}

// ---------------- kernel 3/5: HMMA fused SIREN -------------------------------
// 256 threads = 8 warps; warp w owns rows [16w, 16w+16), full N=128.
// A fragments (3 bf16 splits) live in registers across layers; accumulator
// fragment layout == next-layer A fragment layout (n -> k), so no smem round
// trip for activations. B (weights) double-buffered in smem via cp.async.
__global__ void __launch_bounds__(256, 1)
siren_mma_kernel(int fine,
                 const float* __restrict__ fw, const float* __restrict__ fb,
                 const float* __restrict__ hb,
                 const float* __restrict__ ow, const float* __restrict__ ob) {
    extern __shared__ char smc[];
    uint32_t smb = smem_u32(smc);
    float* ptss = (float*)(smc + SM_PTS);
    float* frs  = (float*)(smc + SM_FR);
    float* phs  = (float*)(smc + SM_PH);
    float* bis  = (float*)(smc + SM_BI);
    float* fws  = (float*)(smc + SM_FW);
    float* fbs  = (float*)(smc + SM_FB);
    float* ows  = (float*)(smc + SM_OW);
    float* obs  = (float*)(smc + SM_OB);

    const float* pts  = fine ? g_points_f : g_points;
    float*       outr = fine ? g_rgbs_f   : g_rgbs_c;

    int tid = threadIdx.x;
    int wid = tid >> 5, lane = tid & 31;
    int m0 = blockIdx.x * MT;
    int batch = m0 / (HW*SS);

    // prefetch layer-1 weights into buffer 0
    for (int i = tid; i < BBUF/16; i += 256)
        cp16(smc + SM_B + i*16, g_wsplit + i*16);
    CP_COMMIT();

    // stage constants
    {
        const float* frq = g_freqs  + batch*FP_DIM;
        const float* phq = g_phases + batch*FP_DIM;
        for (int i = tid; i < FP_DIM; i += 256) { frs[i] = frq[i]; phs[i] = phq[i]; }
        for (int i = tid; i < (NL-1)*HID; i += 256) bis[i] = hb[i];
        for (int i = tid; i < 384; i += 256) { ptss[i] = pts[m0*3 + i]; fws[i] = fw[i]; }
        if (tid < 128) fbs[tid] = fb[tid];
        for (int i = tid; i < 512; i += 256) ows[i] = ow[i];
        if (tid < 4) obs[tid] = ob[tid];
    }
    __syncthreads();

    // A fragments: [split][kstep][reg]
    uint32_t A0[8][4], A1[8][4], A2[8][4];

    // ---- first layer: 3 -> 128 scalar, directly into fragment layout ----
    {
        int rr = lane >> 2;
        int mr0 = wid*16 + rr, mr1 = mr0 + 8;
        float p00 = ptss[mr0*3], p01 = ptss[mr0*3+1], p02 = ptss[mr0*3+2];
        float p10 = ptss[mr1*3], p11 = ptss[mr1*3+1], p12 = ptss[mr1*3+2];
#pragma unroll
        for (int j = 0; j < 16; j++) {
            int n = 8*j + 2*(lane & 3);
            float wa0 = fws[n],   wa1 = fws[128+n],   wa2 = fws[256+n];
            float wb0 = fws[n+1], wb1 = fws[128+n+1], wb2 = fws[256+n+1];
            float ba = fbs[n], bbv = fbs[n+1];
            float fa = frs[n], fbq = frs[n+1], pa = phs[n], pb = phs[n+1];
            float v0 = fast_sin(fa *(ba  + p00*wa0 + p01*wa1 + p02*wa2) + pa);
            float v1 = fast_sin(fbq*(bbv + p00*wb0 + p01*wb1 + p02*wb2) + pb);
            float v2 = fast_sin(fa *(ba  + p10*wa0 + p11*wa1 + p12*wa2) + pa);
            float v3 = fast_sin(fbq*(bbv + p10*wb0 + p11*wb1 + p12*wb2) + pb);
            int s = j >> 1, i0 = (j & 1)*2;
            pack3(v0, v1, A0[s][i0],   A1[s][i0],   A2[s][i0]);
            pack3(v2, v3, A0[s][i0+1], A1[s][i0+1], A2[s][i0+1]);
        }
    }
    CP_WAIT0();
    __syncthreads();

    // lane-constant part of the ldmatrix row address
    int tile = lane >> 3;
    uint32_t rowoff = (uint32_t)((((tile >> 1)*8 + (lane & 7))*WROW) + (tile & 1)*16);

#pragma unroll 1
    for (int l = 1; l < NL; l++) {
        uint32_t bbase = smb + SM_B + (uint32_t)(((l-1) & 1))*BBUF;

        // prefetch next layer's weights into the other buffer
        if (l < NL-1) {
            const char* src = g_wsplit + l*BBUF;
            char* dst = smc + SM_B + (l & 1)*BBUF;
            for (int i = tid; i < BBUF/16; i += 256)
                cp16(dst + i*16, src + i*16);
        }
        CP_COMMIT();

        float acc[16][4];
#pragma unroll
        for (int j = 0; j < 16; j++)
#pragma unroll
            for (int e = 0; e < 4; e++) acc[j][e] = 0.f;

        // mainloop: b-split cb pairs with a-splits {A0[,A1[,A2]]}
#pragma unroll
        for (int cb = 0; cb < 3; cb++) {
#pragma unroll
            for (int s = 0; s < 8; s++) {
                uint32_t ad = bbase + cb*BSPL + s*32 + rowoff;
#pragma unroll
                for (int jp = 0; jp < 8; jp++) {
                    uint32_t t0, t1, t2, t3;
                    LDMX4(t0, t1, t2, t3, ad + jp*(16*WROW));
                    MMA4(acc[2*jp],   A0[s][0], A0[s][1], A0[s][2], A0[s][3], t0, t1);
                    MMA4(acc[2*jp+1], A0[s][0], A0[s][1], A0[s][2], A0[s][3], t2, t3);
                    if (cb < 2) {
                        MMA4(acc[2*jp],   A1[s][0], A1[s][1], A1[s][2], A1[s][3], t0, t1);
                        MMA4(acc[2*jp+1], A1[s][0], A1[s][1], A1[s][2], A1[s][3], t2, t3);
                    }
                    if (cb == 0) {
                        MMA4(acc[2*jp],   A2[s][0], A2[s][1], A2[s][2], A2[s][3], t0, t1);
                        MMA4(acc[2*jp+1], A2[s][0], A2[s][1], A2[s][2], A2[s][3], t2, t3);
                    }
                }
            }
        }

        if (l < NL-1) {
            // epilogue: sin + split back into A fragments
#pragma unroll
            for (int j = 0; j < 16; j++) {
                int n = 8*j + 2*(lane & 3);
                float2 f  = *(const float2*)&frs[l*HID + n];
                float2 p  = *(const float2*)&phs[l*HID + n];
                float2 bb = *(const float2*)&bis[(l-1)*HID + n];
                float v0 = fast_sin(f.x*(acc[j][0] + bb.x) + p.x);
                float v1 = fast_sin(f.y*(acc[j][1] + bb.y) + p.y);
                float v2 = fast_sin(f.x*(acc[j][2] + bb.x) + p.x);
                float v3 = fast_sin(f.y*(acc[j][3] + bb.y) + p.y);
                int s = j >> 1, i0 = (j & 1)*2;
                pack3(v0, v1, A0[s][i0],   A1[s][i0],   A2[s][i0]);
                pack3(v2, v3, A0[s][i0+1], A1[s][i0+1], A2[s][i0+1]);
            }
        } else {
            // final epilogue: sin then fused 128->4 output projection
            float o0[4] = {0.f, 0.f, 0.f, 0.f};
            float o1[4] = {0.f, 0.f, 0.f, 0.f};
#pragma unroll
            for (int j = 0; j < 16; j++) {
                int n = 8*j + 2*(lane & 3);
                float2 f  = *(const float2*)&frs[l*HID + n];
                float2 p  = *(const float2*)&phs[l*HID + n];
                float2 bb = *(const float2*)&bis[(l-1)*HID + n];
                float v0 = fast_sin(f.x*(acc[j][0] + bb.x) + p.x);
                float v1 = fast_sin(f.y*(acc[j][1] + bb.y) + p.y);
                float v2 = fast_sin(f.x*(acc[j][2] + bb.x) + p.x);
                float v3 = fast_sin(f.y*(acc[j][3] + bb.y) + p.y);
                float4 wA = *(const float4*)&ows[n*4];
                float4 wB = *(const float4*)&ows[(n+1)*4];
                o0[0] = fmaf(v0, wA.x, fmaf(v1, wB.x, o0[0]));
                o0[1] = fmaf(v0, wA.y, fmaf(v1, wB.y, o0[1]));
                o0[2] = fmaf(v0, wA.z, fmaf(v1, wB.z, o0[2]));
                o0[3] = fmaf(v0, wA.w, fmaf(v1, wB.w, o0[3]));
                o1[0] = fmaf(v2, wA.x, fmaf(v3, wB.x, o1[0]));
                o1[1] = fmaf(v2, wA.y, fmaf(v3, wB.y, o1[1]));
                o1[2] = fmaf(v2, wA.z, fmaf(v3, wB.z, o1[2]));
                o1[3] = fmaf(v2, wA.w, fmaf(v3, wB.w, o1[3]));
            }
            // reduce across the 4 lanes sharing the same rows (lane bits 0-1)
#pragma unroll
            for (int off = 1; off <= 2; off <<= 1) {
#pragma unroll
                for (int q = 0; q < 4; q++) {
                    o0[q] += __shfl_xor_sync(0xffffffffu, o0[q], off);
                    o1[q] += __shfl_xor_sync(0xffffffffu, o1[q], off);
                }
            }
            if ((lane & 3) == 0) {
                int rr = lane >> 2;
                int row0 = m0 + wid*16 + rr, row1 = row0 + 8;
                float a0 = o0[0] + obs[0], a1 = o0[1] + obs[1];
                float a2 = o0[2] + obs[2], a3 = o0[3] + obs[3];
                float b0 = o1[0] + obs[0], b1 = o1[1] + obs[1];
                float b2 = o1[2] + obs[2], b3 = o1[3] + obs[3];
                float4 q0 = make_float4(1.f/(1.f+expf(-a0)), 1.f/(1.f+expf(-a1)),
                                        1.f/(1.f+expf(-a2)), a3);
                float4 q1 = make_float4(1.f/(1.f+expf(-b0)), 1.f/(1.f+expf(-b1)),
                                        1.f/(1.f+expf(-b2)), b3);
                *(float4*)&outr[row0*4] = q0;
                *(float4*)&outr[row1*4] = q1;
            }
        }
        CP_WAIT0();
        __syncthreads();
    }
}

// ---------------- kernel 4: coarse integration + inverse-CDF sampling -------
__global__ void sample_kernel(const float* __restrict__ c2w,
                              uint32_t kq0, uint32_t kq1) {
    int ray = blockIdx.x * blockDim.x + threadIdx.x;
    if (ray >= NRAYS) return;
    int b = ray / HW;
    int base = ray * SS;

    float z[SS], sg[SS];
    for (int s = 0; s < SS; s++) {
        z[s]  = g_zvals[base + s];
        sg[s] = g_rgbs_c[(base + s)*4 + 3];
    }
    float wgt[SS]; float T = 1.0f;
    for (int s = 0; s < SS; s++) {
        float d = (s < SS-1) ? (z[s+1] - z[s]) : 1e10f;
        float a = 1.0f - expf(-d * fmaxf(sg[s], 0.0f));
        wgt[s] = a * T;
        T *= (1.0f - a + 1e-10f);
    }
    float wq[SS-2]; float sum = 0.0f;
    for (int i = 0; i < SS-2; i++) { wq[i] = wgt[i+1] + 1e-5f; sum += wq[i]; }
    float cdf[SS-1]; cdf[0] = 0.0f; float c = 0.0f;
    for (int i = 0; i < SS-2; i++) { c += wq[i] / sum; cdf[i+1] = c; }
    float bins[SS-1];
    for (int i = 0; i < SS-1; i++) bins[i] = 0.5f * (z[i] + z[i+1]);

    float ox = c2w[b*16 + 3], oy = c2w[b*16 + 7], oz = c2w[b*16 + 11];
    float dx = g_dirs[ray*3+0], dy = g_dirs[ray*3+1], dz = g_dirs[ray*3+2];

    for (int j = 0; j < SS; j++) {
        float u = jax_uniform(kq0, kq1, (uint32_t)(ray*SS + j));
        int ind = SS-1;
        for (int i = 0; i < SS-1; i++) { if (cdf[i] > u) { ind = i; break; } }
        int below = ind - 1; if (below < 0) below = 0; if (below > SS-2) below = SS-2;
        int above = (ind > SS-2) ? (SS-2) : ind;
        float clo = cdf[below], chi = cdf[above];
        float blo = bins[below], bhi = bins[above];
        float den = chi - clo; if (den < 1e-8f) den = 1.0f;
        float fz = blo + (u - clo) / den * (bhi - blo);
        g_finez[base + j] = fz;
        g_points_f[(base + j)*3 + 0] = ox + dx*fz;
        g_points_f[(base + j)*3 + 1] = oy + dy*fz;
        g_points_f[(base + j)*3 + 2] = oz + dz*fz;
    }
}

// ---------------- kernel 6: merge-sort + final integration ------------------
__global__ void final_kernel(float* __restrict__ out) {
    int ray = blockIdx.x * blockDim.x + threadIdx.x;
    if (ray >= NRAYS) return;
    int b = ray / HW, r = ray % HW;
    int h = r / IMG, w = r % IMG;
    int base = ray * SS;

    float z[2*SS]; float4 c[2*SS];
    const float4* rf = reinterpret_cast<const float4*>(g_rgbs_f);
    const float4* rc = reinterpret_cast<const float4*>(g_rgbs_c);
    for (int s = 0; s < SS; s++) { z[s]    = g_finez[base+s]; c[s]    = rf[base+s]; }
    for (int s = 0; s < SS; s++) { z[SS+s] = g_zvals[base+s]; c[SS+s] = rc[base+s]; }

    for (int i = 1; i < 2*SS; i++) {
        float kz = z[i]; float4 kc = c[i];
        int j = i - 1;
        while (j >= 0 && z[j] > kz) { z[j+1] = z[j]; c[j+1] = c[j]; j--; }
        z[j+1] = kz; c[j+1] = kc;
    }

    float T = 1.0f, R = 0.f, G = 0.f, Bc = 0.f, D = 0.f;
    for (int s = 0; s < 2*SS; s++) {
        float d = (s < 2*SS-1) ? (z[s+1] - z[s]) : 1e10f;
        float a = 1.0f - expf(-d * fmaxf(c[s].w, 0.0f));
        float wt = a * T;
        T *= (1.0f - a + 1e-10f);
        R += wt * c[s].x; G += wt * c[s].y; Bc += wt * c[s].z; D += wt * z[s];
    }
    out[((b*3 + 0)*IMG + h)*IMG + w] = R  * 2.0f - 1.0f;
    out[((b*3 + 1)*IMG + h)*IMG + w] = G  * 2.0f - 1.0f;
    out[((b*3 + 2)*IMG + h)*IMG + w] = Bc * 2.0f - 1.0f;
    float x = -1.0f + w * (2.0f/63.0f);
    float y =  1.0f - h * (2.0f/63.0f);
    float n = sqrtf(x*x + y*y + ZC*ZC);
    out[BB*3*HW + ray] = D * (-(ZC/n));
}

// ---------------- launch ------------------------------------------------------
extern "C" void kernel_launch(void* const* d_in, const int* in_sizes, int n_in,
                              void* d_out, int out_size) {
    const float* z    = (const float*)d_in[0];
    const float* c2w  = (const float*)d_in[1];
    const float* mw0  = (const float*)d_in[2];
    const float* mb0  = (const float*)d_in[3];
    const float* mw1  = (const float*)d_in[4];
    const float* mb1  = (const float*)d_in[5];
    const float* mw2  = (const float*)d_in[6];
    const float* mb2  = (const float*)d_in[7];
    const float* fw   = (const float*)d_in[8];
    const float* fb   = (const float*)d_in[9];
    const float* hw_  = (const float*)d_in[10];
    const float* hb   = (const float*)d_in[11];
    const float* ow   = (const float*)d_in[12];
    const float* ob   = (const float*)d_in[13];
    float* out = (float*)d_out;

    uint32_t kp0, kp1, kq0, kq1;
    { uint32_t x0 = 0u, x1 = 0u; tf2x32(0u, 42u, x0, x1); kp0 = x0; kp1 = x1; }
    { uint32_t x0 = 0u, x1 = 1u; tf2x32(0u, 42u, x0, x1); kq0 = x0; kq1 = x1; }

    cudaFuncSetAttribute(siren_mma_kernel,
                         cudaFuncAttributeMaxDynamicSharedMemorySize, SM_TOTAL);

    wsplit_kernel<<<(5*HID*HID + 255)/256, 256>>>(hw_);
    map_kernel   <<<BB, 256>>>(z, mw0, mb0, mw1, mb1, mw2, mb2);
    raygen_kernel<<<NRAYS/256, 256>>>(c2w, kp0, kp1);
    siren_mma_kernel<<<NPTS/MT, 256, SM_TOTAL>>>(0, fw, fb, hb, ow, ob);
    sample_kernel<<<NRAYS/256, 256>>>(c2w, kq0, kq1);
    siren_mma_kernel<<<NPTS/MT, 256, SM_TOTAL>>>(1, fw, fb, hb, ow, ob);
    final_kernel <<<NRAYS/256, 256>>>(out);
}